// round 6
// baseline (speedup 1.0000x reference)
#include <cuda_runtime.h>

#define IN_F   4096
#define OUT_F  11008
#define TOKENS 8

#define THREADS 1024
#define WARPS_PER_BLOCK (THREADS / 32)    // 32
#define GRID 148
#define SMEM_BYTES (TOKENS * IN_F * 4)    // 131072 B x staging

#define KCHUNK     1024                   // columns per work unit
#define KSPLIT     (IN_F / KCHUNK)        // 4
#define CHUNK_F4   (KCHUNK / 4)           // 256 float4 per chunk
#define NUNITS     ((OUT_F / 2) * KSPLIT) // 22016

#define ZERO_BLOCKS ((TOKENS * OUT_F / 4) / 256)  // 86 exactly (float4 stores)
#define PRE_GRID    (ZERO_BLOCKS + TOKENS)        // 94

__device__ float g_sumx[TOKENS];

// --- kernel 1: zero out (float4) + per-token row sums of x -------------------
__global__ void dql_pre(const float* __restrict__ x, float4* __restrict__ out4) {
    int b = blockIdx.x;
    if (b < ZERO_BLOCKS) {
        out4[b * 256 + threadIdx.x] = make_float4(0.f, 0.f, 0.f, 0.f);
    } else {
        __shared__ float red[8];
        int t = b - ZERO_BLOCKS;
        int tid = threadIdx.x;
        float s = 0.f;
        for (int i = tid; i < IN_F; i += 256) s += x[t * IN_F + i];
        #pragma unroll
        for (int off = 16; off; off >>= 1) s += __shfl_xor_sync(0xffffffffu, s, off);
        if ((tid & 31) == 0) red[tid >> 5] = s;
        __syncthreads();
        if (tid < 8) {
            float v = red[tid];
            #pragma unroll
            for (int off = 4; off; off >>= 1) v += __shfl_xor_sync(0xffu, v, off);
            if (tid == 0) g_sumx[t] = v;
        }
    }
}

// --- kernel 2: main streaming dequant-GEMV, 32 warps/SM ----------------------
__global__ __launch_bounds__(THREADS, 1)
void dql_main(const float* __restrict__ x,
              const float* __restrict__ W,
              const int*   __restrict__ Q,
              const float* __restrict__ scales,
              const float* __restrict__ zp,
              const float* __restrict__ bias,
              float*       __restrict__ out) {
    extern __shared__ float xs[];   // [TOKENS][IN_F]

    // Stage x into shared (128 KB), vectorized
    {
        const float4* x4 = (const float4*)x;
        float4* xs4w = (float4*)xs;
        #pragma unroll
        for (int i = threadIdx.x; i < TOKENS * IN_F / 4; i += THREADS)
            xs4w[i] = x4[i];
    }
    __syncthreads();

    const int warp  = threadIdx.x >> 5;
    const int lane  = threadIdx.x & 31;
    const int gwarp = blockIdx.x * WARPS_PER_BLOCK + warp;
    const int nwarp = GRID * WARPS_PER_BLOCK;   // 4736

    const float4* xs4 = (const float4*)xs;

    for (int u = gwarp; u < NUNITS; u += nwarp) {
        const int pair = u >> 2;       // row pair index
        const int kq   = u & 3;        // K chunk index
        const int o0   = pair << 1;
        const int o1   = o0 + 1;
        const float s0 = scales[o0];
        const float s1 = scales[o1];

        const float4* w0 = (const float4*)(W + (size_t)o0 * IN_F + kq * KCHUNK);
        const float4* w1 = (const float4*)(W + (size_t)o1 * IN_F + kq * KCHUNK);
        const int4*   q0 = (const int4*)(Q + (size_t)o0 * IN_F + kq * KCHUNK);
        const int4*   q1 = (const int4*)(Q + (size_t)o1 * IN_F + kq * KCHUNK);
        const float4* xb = xs4 + kq * CHUNK_F4;   // token stride = IN_F/4

        float acc0[TOKENS], acc1[TOKENS];
        #pragma unroll
        for (int t = 0; t < TOKENS; t++) { acc0[t] = 0.f; acc1[t] = 0.f; }

        // 256 float4 per chunk / 32 lanes = 8 iterations; unroll 2 (64-reg cap)
        #pragma unroll 2
        for (int it = 0; it < CHUNK_F4 / 32; ++it) {
            const int c = it * 32 + lane;
            float4 wa = w0[c];
            float4 wb = w1[c];
            int4   qa = q0[c];
            int4   qb = q1[c];

            float4 fa, fb;
            fa.x = fmaf(s0, (float)qa.x, wa.x);
            fa.y = fmaf(s0, (float)qa.y, wa.y);
            fa.z = fmaf(s0, (float)qa.z, wa.z);
            fa.w = fmaf(s0, (float)qa.w, wa.w);
            fb.x = fmaf(s1, (float)qb.x, wb.x);
            fb.y = fmaf(s1, (float)qb.y, wb.y);
            fb.z = fmaf(s1, (float)qb.z, wb.z);
            fb.w = fmaf(s1, (float)qb.w, wb.w);

            #pragma unroll
            for (int t = 0; t < TOKENS; t++) {
                float4 xv = xb[t * (IN_F / 4) + c];
                acc0[t] = fmaf(fa.x, xv.x, acc0[t]);
                acc0[t] = fmaf(fa.y, xv.y, acc0[t]);
                acc0[t] = fmaf(fa.z, xv.z, acc0[t]);
                acc0[t] = fmaf(fa.w, xv.w, acc0[t]);
                acc1[t] = fmaf(fb.x, xv.x, acc1[t]);
                acc1[t] = fmaf(fb.y, xv.y, acc1[t]);
                acc1[t] = fmaf(fb.z, xv.z, acc1[t]);
                acc1[t] = fmaf(fb.w, xv.w, acc1[t]);
            }
        }

        // Segmented fold reduce: 16 values summed across 32 lanes in 31 shfls.
        float v16[16];
        #pragma unroll
        for (int t = 0; t < TOKENS; t++) { v16[2*t] = acc0[t]; v16[2*t+1] = acc1[t]; }
        #pragma unroll
        for (int i = 0; i < 16; i++) v16[i] += __shfl_xor_sync(0xffffffffu, v16[i], 16);
        float v8[8];
        #pragma unroll
        for (int i = 0; i < 8; i++) v8[i] = (lane & 16) ? v16[2*i+1] : v16[2*i];
        #pragma unroll
        for (int i = 0; i < 8; i++) v8[i] += __shfl_xor_sync(0xffffffffu, v8[i], 8);
        float v4[4];
        #pragma unroll
        for (int i = 0; i < 4; i++) v4[i] = (lane & 8) ? v8[2*i+1] : v8[2*i];
        #pragma unroll
        for (int i = 0; i < 4; i++) v4[i] += __shfl_xor_sync(0xffffffffu, v4[i], 4);
        float v2[2];
        #pragma unroll
        for (int i = 0; i < 2; i++) v2[i] = (lane & 4) ? v4[2*i+1] : v4[2*i];
        #pragma unroll
        for (int i = 0; i < 2; i++) v2[i] += __shfl_xor_sync(0xffffffffu, v2[i], 2);
        float v1 = (lane & 2) ? v2[1] : v2[0];
        v1 += __shfl_xor_sync(0xffffffffu, v1, 1);

        if (!(lane & 1)) {
            int r = (lane >> 4) & 1;
            int t = ((lane >> 3) & 1) | (((lane >> 2) & 1) << 1) | (((lane >> 1) & 1) << 2);
            int o = o0 + r;
            if (kq == 0) {
                float sr = r ? s1 : s0;
                v1 += fmaf(-sr * zp[o], __ldg(&g_sumx[t]), bias[o]);
            }
            atomicAdd(out + t * OUT_F + o, v1);
        }
    }
}

extern "C" void kernel_launch(void* const* d_in, const int* in_sizes, int n_in,
                              void* d_out, int out_size) {
    const float* x      = (const float*)d_in[0];
    const float* W      = (const float*)d_in[1];
    const int*   Q      = (const int*)d_in[2];
    const float* scales = (const float*)d_in[3];
    const float* zp     = (const float*)d_in[4];
    const float* bias   = (const float*)d_in[5];
    float* out = (float*)d_out;

    cudaFuncSetAttribute(dql_main, cudaFuncAttributeMaxDynamicSharedMemorySize,
                         SMEM_BYTES);

    dql_pre<<<PRE_GRID, 256>>>(x, (float4*)out);
    dql_main<<<GRID, THREADS, SMEM_BYTES>>>(x, W, Q, scales, zp, bias, out);
}

// round 7
// speedup vs baseline: 1.0455x; 1.0455x over previous
#include <cuda_runtime.h>

#define IN_F   4096
#define OUT_F  11008
#define TOKENS 8

#define THREADS 512
#define WARPS_PER_BLOCK (THREADS / 32)    // 16
#define GRID 148
#define SMEM_BYTES (TOKENS * IN_F * 4)    // 131072 B x staging

__device__ float g_sumx[TOKENS];

// --- kernel 1: per-token row sums of x (8 blocks) ----------------------------
__global__ void dql_pre(const float* __restrict__ x) {
    __shared__ float red[8];
    int t = blockIdx.x;
    int tid = threadIdx.x;
    float s = 0.f;
    for (int i = tid; i < IN_F; i += 256) s += x[t * IN_F + i];
    #pragma unroll
    for (int off = 16; off; off >>= 1) s += __shfl_xor_sync(0xffffffffu, s, off);
    if ((tid & 31) == 0) red[tid >> 5] = s;
    __syncthreads();
    if (tid < 8) {
        float v = red[tid];
        #pragma unroll
        for (int off = 4; off; off >>= 1) v += __shfl_xor_sync(0xffu, v, off);
        if (tid == 0) g_sumx[t] = v;
    }
}

// --- kernel 2: main streaming dequant-GEMV, 1 row per warp-unit --------------
__global__ __launch_bounds__(THREADS, 1)
void dql_main(const float* __restrict__ x,
              const float* __restrict__ W,
              const int*   __restrict__ Q,
              const float* __restrict__ scales,
              const float* __restrict__ zp,
              const float* __restrict__ bias,
              float*       __restrict__ out) {
    extern __shared__ float xs[];   // [TOKENS][IN_F]

    // Stage x into shared (128 KB), vectorized
    {
        const float4* x4 = (const float4*)x;
        float4* xs4w = (float4*)xs;
        #pragma unroll
        for (int i = threadIdx.x; i < TOKENS * IN_F / 4; i += THREADS)
            xs4w[i] = x4[i];
    }
    __syncthreads();

    const int warp  = threadIdx.x >> 5;
    const int lane  = threadIdx.x & 31;
    const int gwarp = blockIdx.x * WARPS_PER_BLOCK + warp;
    const int nwarp = GRID * WARPS_PER_BLOCK;   // 2368

    const float4* xs4 = (const float4*)xs;

    for (int o = gwarp; o < OUT_F; o += nwarp) {
        const float s0 = scales[o];
        const float4* w0 = (const float4*)(W + (size_t)o * IN_F);
        const int4*   q0 = (const int4*)(Q + (size_t)o * IN_F);

        float acc[TOKENS];
        #pragma unroll
        for (int t = 0; t < TOKENS; t++) acc[t] = 0.f;

        // 1024 float4 per row / 32 lanes = 32 iterations; unroll 4 -> 8 LDGs batched
        #pragma unroll 4
        for (int it = 0; it < IN_F / 4 / 32; ++it) {
            const int c = it * 32 + lane;
            float4 wa = w0[c];
            int4   qa = q0[c];

            float4 fa;
            fa.x = fmaf(s0, (float)qa.x, wa.x);
            fa.y = fmaf(s0, (float)qa.y, wa.y);
            fa.z = fmaf(s0, (float)qa.z, wa.z);
            fa.w = fmaf(s0, (float)qa.w, wa.w);

            #pragma unroll
            for (int t = 0; t < TOKENS; t++) {
                float4 xv = xs4[t * (IN_F / 4) + c];
                acc[t] = fmaf(fa.x, xv.x, acc[t]);
                acc[t] = fmaf(fa.y, xv.y, acc[t]);
                acc[t] = fmaf(fa.z, xv.z, acc[t]);
                acc[t] = fmaf(fa.w, xv.w, acc[t]);
            }
        }

        // Segmented fold: 8 token-sums across 32 lanes in 16 shfls.
        // Index bits consumed: lane4 -> t bit0, lane3 -> t bit1, lane2 -> t bit2.
        #pragma unroll
        for (int i = 0; i < 8; i++) acc[i] += __shfl_xor_sync(0xffffffffu, acc[i], 16);
        float v4[4];
        #pragma unroll
        for (int i = 0; i < 4; i++) v4[i] = (lane & 16) ? acc[2*i+1] : acc[2*i];
        #pragma unroll
        for (int i = 0; i < 4; i++) v4[i] += __shfl_xor_sync(0xffffffffu, v4[i], 8);
        float v2[2];
        #pragma unroll
        for (int i = 0; i < 2; i++) v2[i] = (lane & 8) ? v4[2*i+1] : v4[2*i];
        #pragma unroll
        for (int i = 0; i < 2; i++) v2[i] += __shfl_xor_sync(0xffffffffu, v2[i], 4);
        float v1 = (lane & 4) ? v2[1] : v2[0];
        v1 += __shfl_xor_sync(0xffffffffu, v1, 2);
        v1 += __shfl_xor_sync(0xffffffffu, v1, 1);

        if ((lane & 3) == 0) {
            int t = ((lane >> 4) & 1) | (((lane >> 3) & 1) << 1) | (((lane >> 2) & 1) << 2);
            out[t * OUT_F + o] = v1 + fmaf(-s0 * zp[o], __ldg(&g_sumx[t]), bias[o]);
        }
    }
}

extern "C" void kernel_launch(void* const* d_in, const int* in_sizes, int n_in,
                              void* d_out, int out_size) {
    const float* x      = (const float*)d_in[0];
    const float* W      = (const float*)d_in[1];
    const int*   Q      = (const int*)d_in[2];
    const float* scales = (const float*)d_in[3];
    const float* zp     = (const float*)d_in[4];
    const float* bias   = (const float*)d_in[5];
    float* out = (float*)d_out;

    cudaFuncSetAttribute(dql_main, cudaFuncAttributeMaxDynamicSharedMemorySize,
                         SMEM_BYTES);

    dql_pre<<<TOKENS, 256>>>(x);
    dql_main<<<GRID, THREADS, SMEM_BYTES>>>(x, W, Q, scales, zp, bias, out);
}

// round 10
// speedup vs baseline: 1.2379x; 1.1840x over previous
#include <cuda_runtime.h>

#define IN_F   4096
#define OUT_F  11008
#define TOKENS 8

#define THREADS 512
#define WARPS_PER_BLOCK 16
#define GRID 148

#define NPAIR (OUT_F / 2)                 // 5504 row pairs
#define KCHUNK 2048                       // columns per K-half
#define CHUNK_F4 (KCHUNK / 4)             // 512 float4
#define PAIR_SLOTS (WARPS_PER_BLOCK / 2)  // 8 pairs per block per round
#define PAIRS_PER_ROUND (GRID * PAIR_SLOTS)   // 1184
#define ROUNDS ((NPAIR + PAIRS_PER_ROUND - 1) / PAIRS_PER_ROUND)  // 5

// smem: x[8][4096] | sumx[8] | scratch[8 slots][16]
#define SMEM_FLOATS (TOKENS * IN_F + TOKENS + PAIR_SLOTS * 16)
#define SMEM_BYTES  (SMEM_FLOATS * 4)

__global__ __launch_bounds__(THREADS, 1)
void dql_fused(const float* __restrict__ x,
               const float* __restrict__ W,
               const int*   __restrict__ Q,
               const float* __restrict__ scales,
               const float* __restrict__ zp,
               const float* __restrict__ bias,
               float*       __restrict__ out) {
    extern __shared__ float xs[];                 // [TOKENS][IN_F]
    float* sumx    = xs + TOKENS * IN_F;          // [8]
    float* scratch = sumx + TOKENS;               // [8][16]

    // ---- stage x into shared (128 KB), vectorized ----
    {
        const float4* x4 = (const float4*)x;
        float4* xs4w = (float4*)xs;
        #pragma unroll
        for (int i = threadIdx.x; i < TOKENS * IN_F / 4; i += THREADS)
            xs4w[i] = x4[i];
    }
    __syncthreads();

    const int warp  = threadIdx.x >> 5;
    const int lane  = threadIdx.x & 31;

    // ---- in-kernel sumx: warp t reduces token t from shared ----
    if (warp < TOKENS) {
        float s = 0.f;
        #pragma unroll 4
        for (int i = lane; i < IN_F; i += 32) s += xs[warp * IN_F + i];
        #pragma unroll
        for (int off = 16; off; off >>= 1) s += __shfl_xor_sync(0xffffffffu, s, off);
        if (lane == 0) sumx[warp] = s;
    }
    // visibility of sumx is guaranteed by the first __syncthreads inside round 0

    const int slot  = warp >> 1;        // 0..7 : pair slot within block
    const int khalf = warp & 1;         // 0/1  : K half
    const float4* xs4 = (const float4*)xs;

    for (int r = 0; r < ROUNDS; ++r) {
        const int pair = r * PAIRS_PER_ROUND + blockIdx.x * PAIR_SLOTS + slot;
        const bool active = (pair < NPAIR);

        float v1 = 0.f;
        int o0 = 0;
        float s0 = 0.f, s1 = 0.f;

        if (active) {
            o0 = pair << 1;
            const int o1 = o0 + 1;
            s0 = scales[o0];
            s1 = scales[o1];

            const float4* w0 = (const float4*)(W + (size_t)o0 * IN_F + khalf * KCHUNK);
            const float4* w1 = (const float4*)(W + (size_t)o1 * IN_F + khalf * KCHUNK);
            const int4*   q0 = (const int4*)(Q + (size_t)o0 * IN_F + khalf * KCHUNK);
            const int4*   q1 = (const int4*)(Q + (size_t)o1 * IN_F + khalf * KCHUNK);
            const float4* xb = xs4 + khalf * CHUNK_F4;

            float acc0[TOKENS], acc1[TOKENS];
            #pragma unroll
            for (int t = 0; t < TOKENS; t++) { acc0[t] = 0.f; acc1[t] = 0.f; }

            // 512 float4 per K-half / 32 lanes = 16 iterations; unroll 4
            #pragma unroll 4
            for (int it = 0; it < CHUNK_F4 / 32; ++it) {
                const int c = it * 32 + lane;
                float4 wa = w0[c];
                float4 wb = w1[c];
                int4   qa = q0[c];
                int4   qb = q1[c];

                float4 fa, fb;
                fa.x = fmaf(s0, (float)qa.x, wa.x);
                fa.y = fmaf(s0, (float)qa.y, wa.y);
                fa.z = fmaf(s0, (float)qa.z, wa.z);
                fa.w = fmaf(s0, (float)qa.w, wa.w);
                fb.x = fmaf(s1, (float)qb.x, wb.x);
                fb.y = fmaf(s1, (float)qb.y, wb.y);
                fb.z = fmaf(s1, (float)qb.z, wb.z);
                fb.w = fmaf(s1, (float)qb.w, wb.w);

                #pragma unroll
                for (int t = 0; t < TOKENS; t++) {
                    float4 xv = xb[t * (IN_F / 4) + c];
                    acc0[t] = fmaf(fa.x, xv.x, acc0[t]);
                    acc0[t] = fmaf(fa.y, xv.y, acc0[t]);
                    acc0[t] = fmaf(fa.z, xv.z, acc0[t]);
                    acc0[t] = fmaf(fa.w, xv.w, acc0[t]);
                    acc1[t] = fmaf(fb.x, xv.x, acc1[t]);
                    acc1[t] = fmaf(fb.y, xv.y, acc1[t]);
                    acc1[t] = fmaf(fb.z, xv.z, acc1[t]);
                    acc1[t] = fmaf(fb.w, xv.w, acc1[t]);
                }
            }

            // Segmented fold: 16 values summed across 32 lanes in 31 shfls.
            // Result on even lanes: r = lane bit4, t = lane bits 3..1.
            float v16[16];
            #pragma unroll
            for (int t = 0; t < TOKENS; t++) { v16[2*t] = acc0[t]; v16[2*t+1] = acc1[t]; }
            #pragma unroll
            for (int i = 0; i < 16; i++) v16[i] += __shfl_xor_sync(0xffffffffu, v16[i], 16);
            float v8[8];
            #pragma unroll
            for (int i = 0; i < 8; i++) v8[i] = (lane & 16) ? v16[2*i+1] : v16[2*i];
            #pragma unroll
            for (int i = 0; i < 8; i++) v8[i] += __shfl_xor_sync(0xffffffffu, v8[i], 8);
            float v4[4];
            #pragma unroll
            for (int i = 0; i < 4; i++) v4[i] = (lane & 8) ? v8[2*i+1] : v8[2*i];
            #pragma unroll
            for (int i = 0; i < 4; i++) v4[i] += __shfl_xor_sync(0xffffffffu, v4[i], 4);
            float v2[2];
            #pragma unroll
            for (int i = 0; i < 2; i++) v2[i] = (lane & 4) ? v4[2*i+1] : v4[2*i];
            #pragma unroll
            for (int i = 0; i < 2; i++) v2[i] += __shfl_xor_sync(0xffffffffu, v2[i], 2);
            v1 = (lane & 2) ? v2[1] : v2[0];
            v1 += __shfl_xor_sync(0xffffffffu, v1, 1);

            // odd warp deposits its 16 partials in scratch
            if (khalf == 1 && !(lane & 1)) {
                scratch[slot * 16 + (lane >> 1)] = v1;
            }
        }

        __syncthreads();   // scratch ready (also orders sumx on round 0)

        if (active && khalf == 0 && !(lane & 1)) {
            int rr = (lane >> 4) & 1;
            int t  = ((lane >> 3) & 1) | (((lane >> 2) & 1) << 1) | (((lane >> 1) & 1) << 2);
            int o  = o0 + rr;
            float sr = rr ? s1 : s0;
            float total = v1 + scratch[slot * 16 + (lane >> 1)];
            out[t * OUT_F + o] = total + fmaf(-sr * zp[o], sumx[t], bias[o]);
        }

        if (r + 1 < ROUNDS) __syncthreads();   // scratch reuse barrier
    }
}

extern "C" void kernel_launch(void* const* d_in, const int* in_sizes, int n_in,
                              void* d_out, int out_size) {
    const float* x      = (const float*)d_in[0];
    const float* W      = (const float*)d_in[1];
    const int*   Q      = (const int*)d_in[2];
    const float* scales = (const float*)d_in[3];
    const float* zp     = (const float*)d_in[4];
    const float* bias   = (const float*)d_in[5];
    float* out = (float*)d_out;

    cudaFuncSetAttribute(dql_fused, cudaFuncAttributeMaxDynamicSharedMemorySize,
                         SMEM_BYTES);

    dql_fused<<<GRID, THREADS, SMEM_BYTES>>>(x, W, Q, scales, zp, bias, out);
}